// round 4
// baseline (speedup 1.0000x reference)
#include <cuda_runtime.h>
#include <cuda_bf16.h>

static constexpr int BS = 32;
static constexpr int S  = 2048;
static constexpr int H  = 1024;

// Scratch for v[b,h] = sum_k hidden[b,k] * W[k,h]  (device global: no allocs allowed)
__device__ float g_v[BS * H];

// ---------------------------------------------------------------------------
// Stage 0: zero the accumulator (graph replays: must not rely on load-time zero)
// ---------------------------------------------------------------------------
__global__ void zero_v_kernel() {
    g_v[blockIdx.x * blockDim.x + threadIdx.x] = 0.0f;
}

// ---------------------------------------------------------------------------
// Stage 1: v[b,h] = sum_k hidden[b,k] * W[k,h]
// grid: (H/128 h-blocks, BS/8 b-groups, 4 k-chunks), 128 threads.
// Each thread owns one h column, 8 batches, 256 k values; k-chunks reduce via
// atomicAdd (spread addresses -> REDG-rate, cheap).
// ---------------------------------------------------------------------------
__global__ void v_kernel(const float* __restrict__ hidden,
                         const float* __restrict__ W) {
    __shared__ float sh[8][256];
    const int h  = blockIdx.x * 128 + threadIdx.x;
    const int b0 = blockIdx.y * 8;
    const int k0 = blockIdx.z * 256;

    for (int i = threadIdx.x; i < 8 * 256; i += 128) {
        int bb = i >> 8, kk = i & 255;
        sh[bb][kk] = hidden[(b0 + bb) * H + (k0 + kk)];
    }
    __syncthreads();

    float acc[8];
#pragma unroll
    for (int bb = 0; bb < 8; bb++) acc[bb] = 0.0f;

#pragma unroll 4
    for (int kk = 0; kk < 256; kk++) {
        float w = W[(size_t)(k0 + kk) * H + h];   // coalesced across threads (h)
#pragma unroll
        for (int bb = 0; bb < 8; bb++)
            acc[bb] = fmaf(sh[bb][kk], w, acc[bb]);  // smem broadcast
    }

#pragma unroll
    for (int bb = 0; bb < 8; bb++)
        atomicAdd(&g_v[(b0 + bb) * H + h], acc[bb]);
}

// ---------------------------------------------------------------------------
// Stage 2: scores[b,s] = dot(enc[b,s,:], v[b,:])   -- the HBM-bound stage.
// One warp per (b,s). 256-thread blocks = 8 warps covering 8 consecutive s of
// the SAME b (2048 % 8 == 0), so v[b] is staged once per block in smem (4 KB).
// float4 loads, 8 independent loads in flight per lane.
// ---------------------------------------------------------------------------
__global__ void scores_kernel(const float* __restrict__ enc,
                              float* __restrict__ out) {
    __shared__ float4 shv[H / 4];  // 4 KB: v[b]
    const int warp = threadIdx.x >> 5;
    const int lane = threadIdx.x & 31;
    const int b = blockIdx.x >> 8;                  // 256 blocks per batch
    const int s = ((blockIdx.x & 255) << 3) + warp; // 8 rows per block

    const float4* vg = (const float4*)(g_v + b * H);
    for (int i = threadIdx.x; i < H / 4; i += 256) shv[i] = vg[i];
    __syncthreads();

    const float4* e = (const float4*)(enc + ((size_t)b * S + s) * H);

    float a0 = 0.f, a1 = 0.f;
#pragma unroll
    for (int i = 0; i < 8; i++) {
        float4 x = e[lane + 32 * i];
        float4 v = shv[lane + 32 * i];
        a0 = fmaf(x.x, v.x, a0);
        a1 = fmaf(x.y, v.y, a1);
        a0 = fmaf(x.z, v.z, a0);
        a1 = fmaf(x.w, v.w, a1);
    }
    float acc = a0 + a1;
#pragma unroll
    for (int off = 16; off; off >>= 1)
        acc += __shfl_xor_sync(0xffffffffu, acc, off);
    if (lane == 0) out[b * S + s] = acc;
}

// ---------------------------------------------------------------------------
// Stage 3: in-place row softmax over S=2048. One block per batch row.
// (The bias term c[b] = dot(b, hidden[b]) is constant over s -> cancels here,
//  so it is never computed.)
// ---------------------------------------------------------------------------
__global__ void softmax_kernel(float* __restrict__ out) {
    const int b   = blockIdx.x;
    const int tid = threadIdx.x;
    const int warp = tid >> 5, lane = tid & 31;
    float* row = out + b * S;
    __shared__ float red[8];

    float v[8];
    float m = -1e30f;
#pragma unroll
    for (int i = 0; i < 8; i++) {
        v[i] = row[tid + 256 * i];
        m = fmaxf(m, v[i]);
    }
#pragma unroll
    for (int off = 16; off; off >>= 1)
        m = fmaxf(m, __shfl_xor_sync(0xffffffffu, m, off));
    if (lane == 0) red[warp] = m;
    __syncthreads();
    float M = red[0];
#pragma unroll
    for (int w = 1; w < 8; w++) M = fmaxf(M, red[w]);
    __syncthreads();

    float sum = 0.f;
#pragma unroll
    for (int i = 0; i < 8; i++) {
        v[i] = expf(v[i] - M);
        sum += v[i];
    }
#pragma unroll
    for (int off = 16; off; off >>= 1)
        sum += __shfl_xor_sync(0xffffffffu, sum, off);
    if (lane == 0) red[warp] = sum;
    __syncthreads();
    float T = 0.f;
#pragma unroll
    for (int w = 0; w < 8; w++) T += red[w];
    float inv = 1.0f / T;
#pragma unroll
    for (int i = 0; i < 8; i++)
        row[tid + 256 * i] = v[i] * inv;
}

// ---------------------------------------------------------------------------
extern "C" void kernel_launch(void* const* d_in, const int* in_sizes, int n_in,
                              void* d_out, int out_size) {
    // Identify inputs by element count (all four sizes are distinct).
    const float* hidden = nullptr;  // 32768
    const float* enc    = nullptr;  // 67108864
    const float* W      = nullptr;  // 1048576
    for (int i = 0; i < n_in; i++) {
        long sz = in_sizes[i];
        if      (sz == (long)BS * S * H) enc    = (const float*)d_in[i];
        else if (sz == (long)H * H)      W      = (const float*)d_in[i];
        else if (sz == (long)BS * H)     hidden = (const float*)d_in[i];
        // bias (H) intentionally unused: softmax-invariant per-row constant
    }
    float* out = (float*)d_out;  // [BS, S] fp32

    zero_v_kernel<<<(BS * H) / 256, 256>>>();
    v_kernel<<<dim3(H / 128, BS / 8, 4), 128>>>(hidden, W);
    scores_kernel<<<(BS * S) / 8, 256>>>(enc, out);
    softmax_kernel<<<BS, 256>>>(out);
}

// round 5
// speedup vs baseline: 1.8544x; 1.8544x over previous
#include <cuda_runtime.h>
#include <cuda_bf16.h>

static constexpr int BS = 32;
static constexpr int S  = 2048;
static constexpr int H  = 1024;

// Scratch for v[b,h] = sum_k hidden[b,k] * W[k,h]  (device global: no allocs allowed)
__device__ float g_v[BS * H];

// ---------------------------------------------------------------------------
// Stage 0: zero the accumulator (graph replays: must not rely on load-time zero)
// ---------------------------------------------------------------------------
__global__ void zero_v_kernel() {
    g_v[blockIdx.x * blockDim.x + threadIdx.x] = 0.0f;
}

// ---------------------------------------------------------------------------
// Stage 1: v[b,h] = sum_k hidden[b,k] * W[k,h]
// grid: (H/128, BS/8, K/64) = (8, 4, 16) = 512 blocks, 128 threads.
// Each thread owns one h column, 8 batches, 64 k values. Full-ish unroll gives
// ~16 independent W loads in flight per warp; 512 blocks ≈ 14 warps/SM hides
// the rest. k-chunks reduce via atomicAdd (spread addresses -> REDG-rate).
// ---------------------------------------------------------------------------
__global__ void __launch_bounds__(128) v_kernel(const float* __restrict__ hidden,
                                                const float* __restrict__ W) {
    __shared__ float sh[8][64];
    const int h  = blockIdx.x * 128 + threadIdx.x;
    const int b0 = blockIdx.y * 8;
    const int k0 = blockIdx.z * 64;

#pragma unroll
    for (int i = threadIdx.x; i < 8 * 64; i += 128) {
        int bb = i >> 6, kk = i & 63;
        sh[bb][kk] = hidden[(b0 + bb) * H + (k0 + kk)];
    }
    __syncthreads();

    float acc[8];
#pragma unroll
    for (int bb = 0; bb < 8; bb++) acc[bb] = 0.0f;

#pragma unroll 16
    for (int kk = 0; kk < 64; kk++) {
        float w = W[(size_t)(k0 + kk) * H + h];   // coalesced across threads (h)
#pragma unroll
        for (int bb = 0; bb < 8; bb++)
            acc[bb] = fmaf(sh[bb][kk], w, acc[bb]);  // smem broadcast
    }

#pragma unroll
    for (int bb = 0; bb < 8; bb++)
        atomicAdd(&g_v[(b0 + bb) * H + h], acc[bb]);
}

// ---------------------------------------------------------------------------
// Stage 2: scores[b,s] = dot(enc[b,s,:], v[b,:])   -- the HBM-bound stage.
// One warp per (b,s). 256-thread blocks = 8 warps covering 8 consecutive s of
// the SAME b, so v[b] is staged once per block in smem (4 KB). enc is read
// with __ldcs (evict-streaming: 268 MB single-use, keep L2 for g_v/out).
// 8 independent LDG.128 in flight per lane.
// ---------------------------------------------------------------------------
__global__ void __launch_bounds__(256) scores_kernel(const float* __restrict__ enc,
                                                     float* __restrict__ out) {
    __shared__ float4 shv[H / 4];  // 4 KB: v[b]
    const int warp = threadIdx.x >> 5;
    const int lane = threadIdx.x & 31;
    const int b = blockIdx.x >> 8;                  // 256 blocks per batch
    const int s = ((blockIdx.x & 255) << 3) + warp; // 8 rows per block

    const float4* vg = (const float4*)(g_v + b * H);
    for (int i = threadIdx.x; i < H / 4; i += 256) shv[i] = vg[i];
    __syncthreads();

    const float4* e = (const float4*)(enc + ((size_t)b * S + s) * H);

    float a0 = 0.f, a1 = 0.f;
#pragma unroll
    for (int i = 0; i < 8; i++) {
        float4 x = __ldcs(e + lane + 32 * i);
        float4 v = shv[lane + 32 * i];
        a0 = fmaf(x.x, v.x, a0);
        a1 = fmaf(x.y, v.y, a1);
        a0 = fmaf(x.z, v.z, a0);
        a1 = fmaf(x.w, v.w, a1);
    }
    float acc = a0 + a1;
#pragma unroll
    for (int off = 16; off; off >>= 1)
        acc += __shfl_xor_sync(0xffffffffu, acc, off);
    if (lane == 0) out[b * S + s] = acc;
}

// ---------------------------------------------------------------------------
// Stage 3: in-place row softmax over S=2048. One block per batch row.
// (The bias term c[b] = dot(b, hidden[b]) is constant over s -> cancels here,
//  so it is never computed.)
// ---------------------------------------------------------------------------
__global__ void __launch_bounds__(256) softmax_kernel(float* __restrict__ out) {
    const int b    = blockIdx.x;
    const int tid  = threadIdx.x;
    const int warp = tid >> 5, lane = tid & 31;
    float* row = out + b * S;
    __shared__ float red[8];

    float v[8];
    float m = -1e30f;
#pragma unroll
    for (int i = 0; i < 8; i++) {
        v[i] = row[tid + 256 * i];
        m = fmaxf(m, v[i]);
    }
#pragma unroll
    for (int off = 16; off; off >>= 1)
        m = fmaxf(m, __shfl_xor_sync(0xffffffffu, m, off));
    if (lane == 0) red[warp] = m;
    __syncthreads();
    float M = red[0];
#pragma unroll
    for (int w = 1; w < 8; w++) M = fmaxf(M, red[w]);

    float sum = 0.f;
#pragma unroll
    for (int i = 0; i < 8; i++) {
        v[i] = __expf(v[i] - M);
        sum += v[i];
    }
#pragma unroll
    for (int off = 16; off; off >>= 1)
        sum += __shfl_xor_sync(0xffffffffu, sum, off);
    __syncthreads();               // red[] reuse hazard
    if (lane == 0) red[warp] = sum;
    __syncthreads();
    float T = 0.f;
#pragma unroll
    for (int w = 0; w < 8; w++) T += red[w];
    float inv = 1.0f / T;
#pragma unroll
    for (int i = 0; i < 8; i++)
        row[tid + 256 * i] = v[i] * inv;
}

// ---------------------------------------------------------------------------
extern "C" void kernel_launch(void* const* d_in, const int* in_sizes, int n_in,
                              void* d_out, int out_size) {
    // Identify inputs by element count (all four sizes are distinct).
    const float* hidden = nullptr;  // 32768
    const float* enc    = nullptr;  // 67108864
    const float* W      = nullptr;  // 1048576
    for (int i = 0; i < n_in; i++) {
        long sz = in_sizes[i];
        if      (sz == (long)BS * S * H) enc    = (const float*)d_in[i];
        else if (sz == (long)H * H)      W      = (const float*)d_in[i];
        else if (sz == (long)BS * H)     hidden = (const float*)d_in[i];
        // bias (H) intentionally unused: softmax-invariant per-row constant
    }
    float* out = (float*)d_out;  // [BS, S] fp32

    zero_v_kernel<<<(BS * H) / 256, 256>>>();
    v_kernel<<<dim3(H / 128, BS / 8, 16), 128>>>(hidden, W);
    scores_kernel<<<(BS * S) / 8, 256>>>(enc, out);
    softmax_kernel<<<BS, 256>>>(out);
}